// round 2
// baseline (speedup 1.0000x reference)
#include <cuda_runtime.h>
#include <cstdint>
#include <math.h>

#define P_  256
#define L_  64
#define I_  512
#define H_  1024
#define G4  4096   // 4*H
#define OUTD 2

// ---------------- scratch (device globals; no allocations allowed) ----------------
__device__ float g_xw[(size_t)L_ * P_ * G4];  // [L][P][4H] input projections (+bias)
__device__ float g_h[P_ * H_];
__device__ float g_c[P_ * H_];
__device__ float g_final[P_ * H_];
__device__ float g_gates[P_ * G4];
__device__ float g_v[P_ * H_];
__device__ float g_attn[P_ * H_];

// ---------------- tf32 helpers ----------------
__device__ __forceinline__ uint32_t f2tf(float x) {
    uint32_t r;
    asm("cvt.rna.tf32.f32 %0, %1;" : "=r"(r) : "f"(x));
    return r;
}

__device__ __forceinline__ void mma8(float* d,
                                     uint32_t a0, uint32_t a1, uint32_t a2, uint32_t a3,
                                     uint32_t b0, uint32_t b1) {
    asm volatile(
        "mma.sync.aligned.m16n8k8.row.col.f32.tf32.tf32.f32 "
        "{%0,%1,%2,%3},{%4,%5,%6,%7},{%8,%9},{%0,%1,%2,%3};"
        : "+f"(d[0]), "+f"(d[1]), "+f"(d[2]), "+f"(d[3])
        : "r"(a0), "r"(a1), "r"(a2), "r"(a3), "r"(b0), "r"(b1));
}

// =====================================================================
// Kernel 1: fused embedding-gather + input GEMM.
// xw[l][p][n] = sum_k emb[paths[p][l]][k] * W_ih[n][k] + b_ih[n] + b_hh[n]
// M = P*L = 16384 (m = l*P + p), N = 4096, K = 512.
// BM=128, BN=128, BK=32; 256 threads; warps 2x4, warp tile 64x32.
// =====================================================================
__global__ __launch_bounds__(256)
void embed_gemm(const int* __restrict__ paths,
                const float* __restrict__ emb,
                const float* __restrict__ Wih,
                const float* __restrict__ bih,
                const float* __restrict__ bhh) {
    __shared__ uint32_t sA[128][33];
    __shared__ uint32_t sB[128][33];

    const int tid  = threadIdx.x;
    const int lane = tid & 31, warp = tid >> 5;
    const int wm = warp >> 2, wn = warp & 3;          // 2 x 4 warps
    const int m0 = blockIdx.y * 128;
    const int n0 = blockIdx.x * 128;

    // hoist gather tokens: each thread loads 4 float4 of A per K-chunk,
    // row fixed per i across chunks.
    int   arow[4];
    const float* arowp[4];
    int   ac4[4];
#pragma unroll
    for (int i = 0; i < 4; i++) {
        int idx4 = tid + i * 256;
        arow[i] = idx4 >> 3;          // 0..127
        ac4[i]  = (idx4 & 7) * 4;     // 0,4,..,28
        int m = m0 + arow[i];
        int l = m >> 8;               // m / 256 (P=256)
        int p = m & 255;
        int tok = paths[p * L_ + l];
        arowp[i] = emb + (size_t)tok * I_;
    }

    float acc[4][4][4];
#pragma unroll
    for (int a = 0; a < 4; a++)
#pragma unroll
        for (int b = 0; b < 4; b++)
#pragma unroll
            for (int c = 0; c < 4; c++) acc[a][b][c] = 0.f;

    for (int k0 = 0; k0 < I_; k0 += 32) {
#pragma unroll
        for (int i = 0; i < 4; i++) {
            float4 v = *(const float4*)(arowp[i] + k0 + ac4[i]);
            sA[arow[i]][ac4[i] + 0] = f2tf(v.x);
            sA[arow[i]][ac4[i] + 1] = f2tf(v.y);
            sA[arow[i]][ac4[i] + 2] = f2tf(v.z);
            sA[arow[i]][ac4[i] + 3] = f2tf(v.w);
        }
#pragma unroll
        for (int i = 0; i < 4; i++) {
            int idx4 = tid + i * 256;
            int row = idx4 >> 3;
            int c4  = (idx4 & 7) * 4;
            float4 v = *(const float4*)(Wih + (size_t)(n0 + row) * I_ + k0 + c4);
            sB[row][c4 + 0] = f2tf(v.x);
            sB[row][c4 + 1] = f2tf(v.y);
            sB[row][c4 + 2] = f2tf(v.z);
            sB[row][c4 + 3] = f2tf(v.w);
        }
        __syncthreads();

#pragma unroll
        for (int ks = 0; ks < 4; ks++) {
            const int kb = ks * 8;
            uint32_t af[4][4];
#pragma unroll
            for (int mi = 0; mi < 4; mi++) {
                int rb = wm * 64 + mi * 16;
                af[mi][0] = sA[rb + (lane >> 2)][kb + (lane & 3)];
                af[mi][1] = sA[rb + (lane >> 2) + 8][kb + (lane & 3)];
                af[mi][2] = sA[rb + (lane >> 2)][kb + (lane & 3) + 4];
                af[mi][3] = sA[rb + (lane >> 2) + 8][kb + (lane & 3) + 4];
            }
            uint32_t bf[4][2];
#pragma unroll
            for (int ni = 0; ni < 4; ni++) {
                int cb = wn * 32 + ni * 8;
                bf[ni][0] = sB[cb + (lane >> 2)][kb + (lane & 3)];
                bf[ni][1] = sB[cb + (lane >> 2)][kb + (lane & 3) + 4];
            }
#pragma unroll
            for (int mi = 0; mi < 4; mi++)
#pragma unroll
                for (int ni = 0; ni < 4; ni++)
                    mma8(acc[mi][ni], af[mi][0], af[mi][1], af[mi][2], af[mi][3],
                         bf[ni][0], bf[ni][1]);
        }
        __syncthreads();
    }

    // epilogue: add biases, write xw
#pragma unroll
    for (int mi = 0; mi < 4; mi++) {
        int r0 = m0 + wm * 64 + mi * 16 + (lane >> 2);
#pragma unroll
        for (int ni = 0; ni < 4; ni++) {
            int c0 = n0 + wn * 32 + ni * 8 + (lane & 3) * 2;
            float bsum0 = bih[c0] + bhh[c0];
            float bsum1 = bih[c0 + 1] + bhh[c0 + 1];
            g_xw[(size_t)r0 * G4 + c0]           = acc[mi][ni][0] + bsum0;
            g_xw[(size_t)r0 * G4 + c0 + 1]       = acc[mi][ni][1] + bsum1;
            g_xw[(size_t)(r0 + 8) * G4 + c0]     = acc[mi][ni][2] + bsum0;
            g_xw[(size_t)(r0 + 8) * G4 + c0 + 1] = acc[mi][ni][3] + bsum1;
        }
    }
}

// =====================================================================
// Kernel 2: generic M=256 GEMM. D[m][n] = A[m][:]·B[n][:] (+Cadd)(+bias)
// MODE 0: A=g_h,     D=g_gates, Cadd = g_xw slab (t+1)   (recurrent step)
// MODE 1: A=g_final, D=g_v     (v projection)
// MODE 2: A=g_v,     D=g_attn  (out projection)
// BM=64, BN=128, BK=32; 256 threads; warps 2x4, warp tile 32x32.
// All scratch referenced via device globals -> no symbol-address API calls.
// =====================================================================
template <int MODE>
__global__ __launch_bounds__(256)
void gemm256(const float* __restrict__ B, const float* __restrict__ bias,
             int tnext, int Ndim, int K) {
    const float* A = (MODE == 0) ? g_h : (MODE == 1) ? g_final : g_v;
    float*       D = (MODE == 0) ? g_gates : (MODE == 1) ? g_v : g_attn;
    const float* Cadd = (MODE == 0) ? (g_xw + (size_t)tnext * P_ * G4) : nullptr;

    __shared__ uint32_t sA[64][33];
    __shared__ uint32_t sB[128][33];

    const int tid  = threadIdx.x;
    const int lane = tid & 31, warp = tid >> 5;
    const int wm = warp >> 2, wn = warp & 3;
    const int m0 = blockIdx.y * 64;
    const int n0 = blockIdx.x * 128;

    float acc[2][4][4];
#pragma unroll
    for (int a = 0; a < 2; a++)
#pragma unroll
        for (int b = 0; b < 4; b++)
#pragma unroll
            for (int c = 0; c < 4; c++) acc[a][b][c] = 0.f;

    for (int k0 = 0; k0 < K; k0 += 32) {
#pragma unroll
        for (int i = 0; i < 2; i++) {
            int idx4 = tid + i * 256;
            int row = idx4 >> 3;
            int c4  = (idx4 & 7) * 4;
            float4 v = *(const float4*)(A + (size_t)(m0 + row) * K + k0 + c4);
            sA[row][c4 + 0] = f2tf(v.x);
            sA[row][c4 + 1] = f2tf(v.y);
            sA[row][c4 + 2] = f2tf(v.z);
            sA[row][c4 + 3] = f2tf(v.w);
        }
#pragma unroll
        for (int i = 0; i < 4; i++) {
            int idx4 = tid + i * 256;
            int row = idx4 >> 3;
            int c4  = (idx4 & 7) * 4;
            float4 v = *(const float4*)(B + (size_t)(n0 + row) * K + k0 + c4);
            sB[row][c4 + 0] = f2tf(v.x);
            sB[row][c4 + 1] = f2tf(v.y);
            sB[row][c4 + 2] = f2tf(v.z);
            sB[row][c4 + 3] = f2tf(v.w);
        }
        __syncthreads();

#pragma unroll
        for (int ks = 0; ks < 4; ks++) {
            const int kb = ks * 8;
            uint32_t af[2][4];
#pragma unroll
            for (int mi = 0; mi < 2; mi++) {
                int rb = wm * 32 + mi * 16;
                af[mi][0] = sA[rb + (lane >> 2)][kb + (lane & 3)];
                af[mi][1] = sA[rb + (lane >> 2) + 8][kb + (lane & 3)];
                af[mi][2] = sA[rb + (lane >> 2)][kb + (lane & 3) + 4];
                af[mi][3] = sA[rb + (lane >> 2) + 8][kb + (lane & 3) + 4];
            }
            uint32_t bf[4][2];
#pragma unroll
            for (int ni = 0; ni < 4; ni++) {
                int cb = wn * 32 + ni * 8;
                bf[ni][0] = sB[cb + (lane >> 2)][kb + (lane & 3)];
                bf[ni][1] = sB[cb + (lane >> 2)][kb + (lane & 3) + 4];
            }
#pragma unroll
            for (int mi = 0; mi < 2; mi++)
#pragma unroll
                for (int ni = 0; ni < 4; ni++)
                    mma8(acc[mi][ni], af[mi][0], af[mi][1], af[mi][2], af[mi][3],
                         bf[ni][0], bf[ni][1]);
        }
        __syncthreads();
    }

#pragma unroll
    for (int mi = 0; mi < 2; mi++) {
        int r0 = m0 + wm * 32 + mi * 16 + (lane >> 2);
#pragma unroll
        for (int ni = 0; ni < 4; ni++) {
            int c0 = n0 + wn * 32 + ni * 8 + (lane & 3) * 2;
            float v00 = acc[mi][ni][0], v01 = acc[mi][ni][1];
            float v10 = acc[mi][ni][2], v11 = acc[mi][ni][3];
            if (bias) { v00 += bias[c0]; v01 += bias[c0 + 1];
                        v10 += bias[c0]; v11 += bias[c0 + 1]; }
            if (MODE == 0) {
                v00 += Cadd[(size_t)r0 * Ndim + c0];
                v01 += Cadd[(size_t)r0 * Ndim + c0 + 1];
                v10 += Cadd[(size_t)(r0 + 8) * Ndim + c0];
                v11 += Cadd[(size_t)(r0 + 8) * Ndim + c0 + 1];
            }
            D[(size_t)r0 * Ndim + c0]           = v00;
            D[(size_t)r0 * Ndim + c0 + 1]       = v01;
            D[(size_t)(r0 + 8) * Ndim + c0]     = v10;
            D[(size_t)(r0 + 8) * Ndim + c0 + 1] = v11;
        }
    }
}

// =====================================================================
// Kernel 3: LSTM pointwise update (torch gate order i,f,g,o)
// reads gates_t (+c_t), writes h_{t+1}, c_{t+1}; captures final_h.
// t==0 reads from g_xw slab 0 (h0 = 0 -> gates_0 = xw_0), else g_gates.
// =====================================================================
__global__ __launch_bounds__(256)
void lstm_pointwise(const int* __restrict__ lengths, int t) {
    int idx = blockIdx.x * 256 + threadIdx.x;   // < P*H
    int p = idx >> 10;
    int j = idx & (H_ - 1);
    const float* gates = (t == 0) ? g_xw : g_gates;
    const float* gp = gates + (size_t)p * G4 + j;
    float ig = gp[0];
    float fg = gp[H_];
    float gg = gp[2 * H_];
    float og = gp[3 * H_];
    float c_old = (t == 0) ? 0.f : g_c[idx];

    float i_s = 1.f / (1.f + expf(-ig));
    float f_s = 1.f / (1.f + expf(-fg));
    float o_s = 1.f / (1.f + expf(-og));
    float c_new = f_s * c_old + i_s * tanhf(gg);
    float h = o_s * tanhf(c_new);

    g_c[idx] = c_new;
    g_h[idx] = h;
    if (lengths[p] == t + 1) g_final[idx] = h;
}

// =====================================================================
// Kernel 4: max-pool over P + final linear + sigmoid
// =====================================================================
__global__ __launch_bounds__(1024)
void pool_out(const float* __restrict__ Wlin, const float* __restrict__ blin,
              float* __restrict__ out) {
    __shared__ float sp[H_];
    __shared__ float red[32];
    int j = threadIdx.x;  // 1024 threads
    float m = -INFINITY;
    for (int p = 0; p < P_; ++p) m = fmaxf(m, g_attn[p * H_ + j]);
    sp[j] = m;
    __syncthreads();

    for (int o = 0; o < OUTD; ++o) {
        float v = sp[j] * Wlin[o * H_ + j];
#pragma unroll
        for (int s = 16; s; s >>= 1) v += __shfl_down_sync(0xffffffffu, v, s);
        if ((j & 31) == 0) red[j >> 5] = v;
        __syncthreads();
        if (j < 32) {
            float w = red[j];
#pragma unroll
            for (int s = 16; s; s >>= 1) w += __shfl_down_sync(0xffffffffu, w, s);
            if (j == 0) out[o] = 1.f / (1.f + expf(-(w + blin[o])));
        }
        __syncthreads();
    }
}

// =====================================================================
extern "C" void kernel_launch(void* const* d_in, const int* in_sizes, int n_in,
                              void* d_out, int out_size) {
    (void)in_sizes; (void)n_in; (void)out_size;
    const int*   paths   = (const int*)d_in[0];
    const int*   lengths = (const int*)d_in[1];
    const float* emb     = (const float*)d_in[2];
    const float* Wih     = (const float*)d_in[3];
    const float* Whh     = (const float*)d_in[4];
    const float* bih     = (const float*)d_in[5];
    const float* bhh     = (const float*)d_in[6];
    const float* Win     = (const float*)d_in[7];
    const float* bin     = (const float*)d_in[8];
    const float* Wout    = (const float*)d_in[9];
    const float* bout    = (const float*)d_in[10];
    const float* Wlin    = (const float*)d_in[11];
    const float* blin    = (const float*)d_in[12];
    float* out = (float*)d_out;

    // Phase A: embed + input projection for all timesteps
    embed_gemm<<<dim3(32, 128), 256>>>(paths, emb, Wih, bih, bhh);

    // Phase B: recurrence. gates_0 = xw slab 0 (h0 = 0), so step-0 GEMM is skipped.
    for (int t = 0; t < L_; ++t) {
        lstm_pointwise<<<(P_ * H_) / 256, 256>>>(lengths, t);
        if (t < L_ - 1) {
            gemm256<0><<<dim3(32, 4), 256>>>(Whh, nullptr, t + 1, G4, H_);
        }
    }

    // Phase C: attention (seq_len=1 -> softmax == 1 -> ctx == v). q,k dead.
    gemm256<1><<<dim3(8, 4), 256>>>(Win + 2 * H_ * H_, bin + 2 * H_, 0, H_, H_);
    gemm256<2><<<dim3(8, 4), 256>>>(Wout, bout, 0, H_, H_);

    // Phase D: max-pool over paths + output layer
    pool_out<<<1, 1024>>>(Wlin, blin, out);
}

// round 4
// speedup vs baseline: 2.8889x; 2.8889x over previous
#include <cuda_runtime.h>
#include <cuda_bf16.h>
#include <cstdint>
#include <math.h>

#define P_  256
#define L_  64
#define I_  512
#define H_  1024
#define G4  4096
#define OUTD 2
#define SPAD 40           // halves per 32-half row slot (+8 pad) = 80B, conflict-free & 16B-mult

using bf16 = __nv_bfloat16;

// ---------------- device-global scratch ----------------
__device__ float g_xw[(size_t)L_ * P_ * G4];   // blocked: [l][p][x*128 + gate*32 + c]
__device__ bf16  g_embb[(size_t)50000 * I_];
__device__ bf16  g_wihb[(size_t)G4 * I_];
__device__ bf16  g_whhb[(size_t)G4 * H_];      // blocked panels: [x][gate*32+r][k]
__device__ bf16  g_winvb[(size_t)H_ * H_];     // v-part of in_proj
__device__ bf16  g_woutb[(size_t)H_ * H_];
__device__ bf16  g_hb[P_ * H_];
__device__ float g_c[P_ * H_];
__device__ bf16  g_finalb[P_ * H_];
__device__ bf16  g_vb[P_ * H_];
__device__ float g_attn[P_ * H_];

// ---------------- asm helpers ----------------
__device__ __forceinline__ void cpa16(uint32_t d, const void* s) {
    asm volatile("cp.async.cg.shared.global [%0], [%1], 16;\n" :: "r"(d), "l"(s));
}
__device__ __forceinline__ void cpcommit() { asm volatile("cp.async.commit_group;\n"); }
template <int N> __device__ __forceinline__ void cpwait() {
    asm volatile("cp.async.wait_group %0;\n" :: "n"(N));
}
__device__ __forceinline__ void mma16(float* d, uint32_t a0, uint32_t a1, uint32_t a2,
                                      uint32_t a3, uint32_t b0, uint32_t b1) {
    asm volatile(
        "mma.sync.aligned.m16n8k16.row.col.f32.bf16.bf16.f32 "
        "{%0,%1,%2,%3},{%4,%5,%6,%7},{%8,%9},{%0,%1,%2,%3};"
        : "+f"(d[0]), "+f"(d[1]), "+f"(d[2]), "+f"(d[3])
        : "r"(a0), "r"(a1), "r"(a2), "r"(a3), "r"(b0), "r"(b1));
}
__device__ __forceinline__ float sigf(float x) { return 1.f / (1.f + expf(-x)); }

// fragment math shared by all GEMMs. Warp tile = (MI*16) x 32, 2 k16-steps per BK=32 stage.
template <int MI>
__device__ __forceinline__ void mma_stage(const bf16* A, const bf16* B,
                                          int wm, int wn, int lane, float acc[][4][4]) {
    const int r = lane >> 2, cp = (lane & 3) * 2;
#pragma unroll
    for (int ks = 0; ks < 2; ++ks) {
        const int kb = ks * 16;
        uint32_t a[MI][4];
#pragma unroll
        for (int mi = 0; mi < MI; ++mi) {
            const bf16* ap = A + (wm * MI * 16 + mi * 16 + r) * SPAD + kb + cp;
            a[mi][0] = *(const uint32_t*)ap;
            a[mi][1] = *(const uint32_t*)(ap + 8 * SPAD);
            a[mi][2] = *(const uint32_t*)(ap + 8);
            a[mi][3] = *(const uint32_t*)(ap + 8 * SPAD + 8);
        }
        uint32_t b[4][2];
#pragma unroll
        for (int ni = 0; ni < 4; ++ni) {
            const bf16* bp = B + (wn * 32 + ni * 8 + r) * SPAD + kb + cp;
            b[ni][0] = *(const uint32_t*)bp;
            b[ni][1] = *(const uint32_t*)(bp + 8);
        }
#pragma unroll
        for (int mi = 0; mi < MI; ++mi)
#pragma unroll
            for (int ni = 0; ni < 4; ++ni)
                mma16(acc[mi][ni], a[mi][0], a[mi][1], a[mi][2], a[mi][3],
                      b[ni][0], b[ni][1]);
    }
}

// =====================================================================
// Prep: convert emb/Wih to bf16; Whh to bf16 reordered into gate-blocked
// panels; Win(v-part)/Wout to bf16. One flat-index kernel, 4 elems/thread.
// =====================================================================
__global__ __launch_bounds__(256)
void conv_all(const float* __restrict__ emb, const float* __restrict__ Wih,
              const float* __restrict__ Whh, const float* __restrict__ Win,
              const float* __restrict__ Wout) {
    const size_t NE = (size_t)50000 * I_;     // 25,600,000
    const size_t NW1 = (size_t)G4 * I_;       //  2,097,152
    const size_t NW2 = (size_t)G4 * H_;       //  4,194,304
    const size_t NV  = (size_t)H_ * H_;       //  1,048,576
    size_t i4 = ((size_t)blockIdx.x * 256 + threadIdx.x) * 4;
    float4 v; bf16* dst;
    if (i4 < NE) { v = *(const float4*)(emb + i4); dst = g_embb + i4; }
    else if ((i4 -= NE) < NW1) { v = *(const float4*)(Wih + i4); dst = g_wihb + i4; }
    else if ((i4 -= NW1) < NW2) {
        size_t k = i4 & (H_ - 1), np = i4 >> 10;
        size_t x = np >> 7, g = (np >> 5) & 3, r = np & 31;
        size_t n = g * H_ + x * 32 + r;
        v = *(const float4*)(Whh + n * H_ + k); dst = g_whhb + i4;
    }
    else if ((i4 -= NW2) < NV) { v = *(const float4*)(Win + (size_t)2 * H_ * H_ + i4); dst = g_winvb + i4; }
    else if ((i4 -= NV) < NV)  { v = *(const float4*)(Wout + i4); dst = g_woutb + i4; }
    else return;
    dst[0] = __float2bfloat16(v.x); dst[1] = __float2bfloat16(v.y);
    dst[2] = __float2bfloat16(v.z); dst[3] = __float2bfloat16(v.w);
}

// =====================================================================
// Embed + input GEMM (bf16, cp.async 2-stage).
// M=16384 (m=l*256+p), N=4096, K=512. BM=128,BN=128,BK=32. 256 thr, warps 2x4.
// Writes g_xw in blocked layout with bias folded in.
// =====================================================================
__global__ __launch_bounds__(256)
void embed_gemm(const int* __restrict__ paths,
                const float* __restrict__ bih, const float* __restrict__ bhh) {
    constexpr int STG = (128 + 128) * SPAD;          // halves per stage
    __shared__ __align__(16) bf16 smem[2 * STG];
    const uint32_t sbase = (uint32_t)__cvta_generic_to_shared(smem);

    const int tid = threadIdx.x, lane = tid & 31, warp = tid >> 5;
    const int wm = warp >> 2, wn = warp & 3;
    const int m0 = blockIdx.y * 128, n0 = blockIdx.x * 128;
    const int l = m0 >> 8;

    // gather row pointers (2 A-chunk rows per thread, fixed across K)
    const bf16* arowp[2];
    int arow[2], acc4[2];
#pragma unroll
    for (int j = 0; j < 2; ++j) {
        int ch = tid + j * 256;
        arow[j] = ch >> 2; acc4[j] = (ch & 3) * 8;
        int p = (m0 & 255) + arow[j];
        arowp[j] = g_embb + (size_t)paths[p * L_ + l] * I_;
    }
    const bf16* Bb = g_wihb + (size_t)n0 * I_;

    float acc[4][4][4];
#pragma unroll
    for (int a = 0; a < 4; a++)
#pragma unroll
        for (int b = 0; b < 4; b++)
#pragma unroll
            for (int c = 0; c < 4; c++) acc[a][b][c] = 0.f;

    auto load = [&](int s, int k0) {
        uint32_t sa = sbase + s * STG * 2;
        uint32_t sb = sa + 128 * SPAD * 2;
#pragma unroll
        for (int j = 0; j < 2; ++j)
            cpa16(sa + (arow[j] * SPAD + acc4[j]) * 2, arowp[j] + k0 + acc4[j]);
#pragma unroll
        for (int j = 0; j < 2; ++j) {
            int ch = tid + j * 256;
            int row = ch >> 2, cc = (ch & 3) * 8;
            cpa16(sb + (row * SPAD + cc) * 2, Bb + (size_t)row * I_ + k0 + cc);
        }
    };

    load(0, 0); cpcommit();
    for (int it = 0; it < 16; ++it) {
        if (it + 1 < 16) load((it + 1) & 1, (it + 1) * 32);
        cpcommit();
        cpwait<1>();
        __syncthreads();
        const bf16* A = smem + (it & 1) * STG;
        mma_stage<4>(A, A + 128 * SPAD, wm, wn, lane, acc);
        __syncthreads();
    }

    // epilogue: bias + blocked write
#pragma unroll
    for (int mi = 0; mi < 4; ++mi) {
        int m = m0 + wm * 64 + mi * 16 + (lane >> 2);
        int p = m & 255;
        float* xr0 = g_xw + ((size_t)l * P_ + p) * G4;
        float* xr1 = xr0 + 8 * G4;   // row m+8 (same l since 16-row frags stay in-block)
#pragma unroll
        for (int ni = 0; ni < 4; ++ni) {
            int n = n0 + wn * 32 + ni * 8 + (lane & 3) * 2;
            int x = (n & (H_ - 1)) >> 5, g = n >> 10, c = n & 31;
            int off = x * 128 + g * 32 + c;
            float b0 = bih[n] + bhh[n], b1 = bih[n + 1] + bhh[n + 1];
            xr0[off]     = acc[mi][ni][0] + b0;
            xr0[off + 1] = acc[mi][ni][1] + b1;
            xr1[off]     = acc[mi][ni][2] + b0;
            xr1[off + 1] = acc[mi][ni][3] + b1;
        }
    }
}

// =====================================================================
// Step 0 pointwise: gates = xw[0] (h0=0, c0=0)
// =====================================================================
__global__ __launch_bounds__(256)
void pointwise0(const int* __restrict__ lengths) {
    int idx = blockIdx.x * 256 + threadIdx.x;      // < P*H
    int p = idx >> 10, j = idx & (H_ - 1);
    int x = j >> 5, r = j & 31;
    const float* base = g_xw + (size_t)p * G4 + x * 128;
    float ig = base[r], gg = base[64 + r], og = base[96 + r];
    float c_new = sigf(ig) * tanhf(gg);
    float h = sigf(og) * tanhf(c_new);
    g_c[idx] = c_new;
    g_hb[idx] = __float2bfloat16(h);
    if (lengths[p] == 1) g_finalb[idx] = __float2bfloat16(h);
}

// =====================================================================
// Fused LSTM step t (t=1..63): gates = h_{t-1} @ Whh^T + xw[t]; nonlinearity
// fused in epilogue. CTA x owns hidden cols [x*32, x*32+32) for ALL 4 gates
// (gate-blocked Whh panel). BM=64, BN=128(=4 gates x 32), BK=32, 3 stages.
// =====================================================================
__global__ __launch_bounds__(256)
void lstm_step(int t, const int* __restrict__ lengths) {
    constexpr int STG = (64 + 128) * SPAD;         // halves per stage
    __shared__ __align__(16) bf16 smem[3 * STG];   // 46080 B; reused as fp32 gates tile
    const uint32_t sbase = (uint32_t)__cvta_generic_to_shared(smem);

    const int tid = threadIdx.x, lane = tid & 31, warp = tid >> 5;
    const int wm = warp >> 2, wn = warp & 3;
    const int x = blockIdx.x;                       // hidden group
    const int p0 = blockIdx.y * 64;

    const bf16* Ab = g_hb + (size_t)p0 * H_;
    const bf16* Bb = g_whhb + (size_t)x * 128 * H_;

    float acc[2][4][4];
#pragma unroll
    for (int a = 0; a < 2; a++)
#pragma unroll
        for (int b = 0; b < 4; b++)
#pragma unroll
            for (int c = 0; c < 4; c++) acc[a][b][c] = 0.f;

    auto load = [&](int s, int k0) {
        uint32_t sa = sbase + s * STG * 2;
        uint32_t sb = sa + 64 * SPAD * 2;
        {   // A: 256 chunks, 1/thread
            int row = tid >> 2, cc = (tid & 3) * 8;
            cpa16(sa + (row * SPAD + cc) * 2, Ab + (size_t)row * H_ + k0 + cc);
        }
#pragma unroll
        for (int j = 0; j < 2; ++j) {   // B: 512 chunks, 2/thread
            int ch = tid + j * 256;
            int row = ch >> 2, cc = (ch & 3) * 8;
            cpa16(sb + (row * SPAD + cc) * 2, Bb + (size_t)row * H_ + k0 + cc);
        }
    };

    load(0, 0); cpcommit();
    load(1, 32); cpcommit();
    for (int it = 0; it < 32; ++it) {
        if (it + 2 < 32) load((it + 2) % 3, (it + 2) * 32);
        cpcommit();
        cpwait<2>();
        __syncthreads();
        const bf16* A = smem + (it % 3) * STG;
        mma_stage<2>(A, A + 64 * SPAD, wm, wn, lane, acc);
        __syncthreads();
    }

    // ---- fused LSTM epilogue ----
    float* sG = (float*)smem;                       // [64][128]
#pragma unroll
    for (int mi = 0; mi < 2; ++mi) {
        int r0 = wm * 32 + mi * 16 + (lane >> 2);
#pragma unroll
        for (int ni = 0; ni < 4; ++ni) {
            int c0 = wn * 32 + ni * 8 + (lane & 3) * 2;
            sG[r0 * 128 + c0]           = acc[mi][ni][0];
            sG[r0 * 128 + c0 + 1]       = acc[mi][ni][1];
            sG[(r0 + 8) * 128 + c0]     = acc[mi][ni][2];
            sG[(r0 + 8) * 128 + c0 + 1] = acc[mi][ni][3];
        }
    }
    __syncthreads();

    const int r = lane;
    const float* xwp = g_xw + ((size_t)t * P_ + p0) * G4 + x * 128;
#pragma unroll
    for (int wi = 0; wi < 8; ++wi) {
        int p = (tid >> 5) + wi * 8;                // 0..63
        const float* xr = xwp + (size_t)p * G4;
        float ig = sG[p * 128 + r]       + xr[r];
        float fg = sG[p * 128 + 32 + r]  + xr[32 + r];
        float gg = sG[p * 128 + 64 + r]  + xr[64 + r];
        float og = sG[p * 128 + 96 + r]  + xr[96 + r];
        int gi = (p0 + p) * H_ + x * 32 + r;
        float c_new = sigf(fg) * g_c[gi] + sigf(ig) * tanhf(gg);
        float h = sigf(og) * tanhf(c_new);
        g_c[gi] = c_new;
        g_hb[gi] = __float2bfloat16(h);
        if (lengths[p0 + p] == t + 1) g_finalb[gi] = __float2bfloat16(h);
    }
}

// =====================================================================
// Attention-path GEMMs (seq_len=1 => softmax==1 => ctx==v; q,k dead).
// MODE 0: g_vb   = g_finalb @ Wv^T  + b_v     (bf16 out)
// MODE 1: g_attn = g_vb     @ Wout^T + b_out  (fp32 out)
// Same 3-stage pipeline, BM=64, BN=128, K=1024.
// =====================================================================
template <int MODE>
__global__ __launch_bounds__(256)
void gemm_attn(const float* __restrict__ bias) {
    constexpr int STG = (64 + 128) * SPAD;
    __shared__ __align__(16) bf16 smem[3 * STG];
    const uint32_t sbase = (uint32_t)__cvta_generic_to_shared(smem);

    const int tid = threadIdx.x, lane = tid & 31, warp = tid >> 5;
    const int wm = warp >> 2, wn = warp & 3;
    const int n0 = blockIdx.x * 128, p0 = blockIdx.y * 64;

    const bf16* Ab = (MODE ? g_vb : g_finalb) + (size_t)p0 * H_;
    const bf16* Bb = (MODE ? g_woutb : g_winvb) + (size_t)n0 * H_;

    float acc[2][4][4];
#pragma unroll
    for (int a = 0; a < 2; a++)
#pragma unroll
        for (int b = 0; b < 4; b++)
#pragma unroll
            for (int c = 0; c < 4; c++) acc[a][b][c] = 0.f;

    auto load = [&](int s, int k0) {
        uint32_t sa = sbase + s * STG * 2;
        uint32_t sb = sa + 64 * SPAD * 2;
        {
            int row = tid >> 2, cc = (tid & 3) * 8;
            cpa16(sa + (row * SPAD + cc) * 2, Ab + (size_t)row * H_ + k0 + cc);
        }
#pragma unroll
        for (int j = 0; j < 2; ++j) {
            int ch = tid + j * 256;
            int row = ch >> 2, cc = (ch & 3) * 8;
            cpa16(sb + (row * SPAD + cc) * 2, Bb + (size_t)row * H_ + k0 + cc);
        }
    };

    load(0, 0); cpcommit();
    load(1, 32); cpcommit();
    for (int it = 0; it < 32; ++it) {
        if (it + 2 < 32) load((it + 2) % 3, (it + 2) * 32);
        cpcommit();
        cpwait<2>();
        __syncthreads();
        const bf16* A = smem + (it % 3) * STG;
        mma_stage<2>(A, A + 64 * SPAD, wm, wn, lane, acc);
        __syncthreads();
    }

#pragma unroll
    for (int mi = 0; mi < 2; ++mi) {
        int r0 = p0 + wm * 32 + mi * 16 + (lane >> 2);
#pragma unroll
        for (int ni = 0; ni < 4; ++ni) {
            int c0 = n0 + wn * 32 + ni * 8 + (lane & 3) * 2;
            float v00 = acc[mi][ni][0] + bias[c0];
            float v01 = acc[mi][ni][1] + bias[c0 + 1];
            float v10 = acc[mi][ni][2] + bias[c0];
            float v11 = acc[mi][ni][3] + bias[c0 + 1];
            if (MODE == 0) {
                *(__nv_bfloat162*)&g_vb[(size_t)r0 * H_ + c0] =
                    __nv_bfloat162(__float2bfloat16(v00), __float2bfloat16(v01));
                *(__nv_bfloat162*)&g_vb[(size_t)(r0 + 8) * H_ + c0] =
                    __nv_bfloat162(__float2bfloat16(v10), __float2bfloat16(v11));
            } else {
                g_attn[(size_t)r0 * H_ + c0]           = v00;
                g_attn[(size_t)r0 * H_ + c0 + 1]       = v01;
                g_attn[(size_t)(r0 + 8) * H_ + c0]     = v10;
                g_attn[(size_t)(r0 + 8) * H_ + c0 + 1] = v11;
            }
        }
    }
}

// =====================================================================
// Max-pool over P + final linear + sigmoid
// =====================================================================
__global__ __launch_bounds__(1024)
void pool_out(const float* __restrict__ Wlin, const float* __restrict__ blin,
              float* __restrict__ out) {
    __shared__ float sp[H_];
    __shared__ float red[32];
    int j = threadIdx.x;
    float m = -INFINITY;
    for (int p = 0; p < P_; ++p) m = fmaxf(m, g_attn[p * H_ + j]);
    sp[j] = m;
    __syncthreads();
    for (int o = 0; o < OUTD; ++o) {
        float v = sp[j] * Wlin[o * H_ + j];
#pragma unroll
        for (int s = 16; s; s >>= 1) v += __shfl_down_sync(0xffffffffu, v, s);
        if ((j & 31) == 0) red[j >> 5] = v;
        __syncthreads();
        if (j < 32) {
            float w = red[j];
#pragma unroll
            for (int s = 16; s; s >>= 1) w += __shfl_down_sync(0xffffffffu, w, s);
            if (j == 0) out[o] = 1.f / (1.f + expf(-(w + blin[o])));
        }
        __syncthreads();
    }
}

// =====================================================================
extern "C" void kernel_launch(void* const* d_in, const int* in_sizes, int n_in,
                              void* d_out, int out_size) {
    (void)in_sizes; (void)n_in; (void)out_size;
    const int*   paths   = (const int*)d_in[0];
    const int*   lengths = (const int*)d_in[1];
    const float* emb     = (const float*)d_in[2];
    const float* Wih     = (const float*)d_in[3];
    const float* Whh     = (const float*)d_in[4];
    const float* bih     = (const float*)d_in[5];
    const float* bhh     = (const float*)d_in[6];
    const float* Win     = (const float*)d_in[7];
    const float* bin     = (const float*)d_in[8];
    const float* Wout    = (const float*)d_in[9];
    const float* bout    = (const float*)d_in[10];
    const float* Wlin    = (const float*)d_in[11];
    const float* blin    = (const float*)d_in[12];
    float* out = (float*)d_out;

    // prep: bf16 conversion + Whh gate-blocked reorder (33,988,608 elems / 4 / 256)
    conv_all<<<33192, 256>>>(emb, Wih, Whh, Win, Wout);

    // phase A: embed + input projection, blocked layout, bias folded
    embed_gemm<<<dim3(32, 128), 256>>>(paths, bih, bhh);

    // phase B: recurrence (step 0 is pointwise-only since h0=0)
    pointwise0<<<1024, 256>>>(lengths);
    for (int t = 1; t < L_; ++t)
        lstm_step<<<dim3(32, 4), 256>>>(t, lengths);

    // phase C: v-proj + out-proj
    gemm_attn<0><<<dim3(8, 4), 256>>>(bin + 2 * H_);
    gemm_attn<1><<<dim3(8, 4), 256>>>(bout);

    // phase D: pool + output
    pool_out<<<1, 1024>>>(Wlin, blin, out);
}

// round 5
// speedup vs baseline: 3.6138x; 1.2509x over previous
#include <cuda_runtime.h>
#include <cuda_bf16.h>
#include <cstdint>
#include <math.h>

#define P_  256
#define L_  64
#define I_  512
#define H_  1024
#define G4  4096
#define OUTD 2
#define SPAD 40            // embed/attn kernels: halves per 32-half slot (+8 pad)
#define NPER 128           // persistent grid size
#define B_PITCH 1048       // persist B smem pitch (halves): 524 words, 12-bank row step
#define A_PITCH 72         // persist A smem pitch (halves): 36 words, 4-bank row step
#define BKP 64             // persist K-chunk

using bf16 = __nv_bfloat16;

// ---------------- device-global scratch ----------------
__device__ float g_xw[(size_t)L_ * NPER * P_ * 32];  // [l][panel x][p][g*8+c]
__device__ bf16  g_embb[(size_t)50000 * I_];
__device__ bf16  g_wihb[(size_t)G4 * I_];
__device__ bf16  g_whhb[(size_t)G4 * H_];  // panels: [x][g*8+c][k]  (32 rows x 1024)
__device__ bf16  g_winvb[(size_t)H_ * H_];
__device__ bf16  g_woutb[(size_t)H_ * H_];
__device__ bf16  g_hbuf0[P_ * H_];
__device__ bf16  g_hbuf1[P_ * H_];
__device__ bf16  g_finalb[P_ * H_];
__device__ bf16  g_vb[P_ * H_];
__device__ float g_attn[P_ * H_];
__device__ unsigned g_barcnt;
__device__ unsigned g_bargen;

// ---------------- asm helpers ----------------
__device__ __forceinline__ void cpa16(uint32_t d, const void* s) {
    asm volatile("cp.async.cg.shared.global [%0], [%1], 16;\n" :: "r"(d), "l"(s));
}
__device__ __forceinline__ void cpcommit() { asm volatile("cp.async.commit_group;\n"); }
template <int N> __device__ __forceinline__ void cpwait() {
    asm volatile("cp.async.wait_group %0;\n" :: "n"(N));
}
__device__ __forceinline__ void mma16(float* d, uint32_t a0, uint32_t a1, uint32_t a2,
                                      uint32_t a3, uint32_t b0, uint32_t b1) {
    asm volatile(
        "mma.sync.aligned.m16n8k16.row.col.f32.bf16.bf16.f32 "
        "{%0,%1,%2,%3},{%4,%5,%6,%7},{%8,%9},{%0,%1,%2,%3};"
        : "+f"(d[0]), "+f"(d[1]), "+f"(d[2]), "+f"(d[3])
        : "r"(a0), "r"(a1), "r"(a2), "r"(a3), "r"(b0), "r"(b1));
}
__device__ __forceinline__ float sigf(float x) { return 1.f / (1.f + expf(-x)); }

// fragment math for embed/attn kernels (SPAD layout)
template <int MI>
__device__ __forceinline__ void mma_stage(const bf16* A, const bf16* B,
                                          int wm, int wn, int lane, float acc[][4][4]) {
    const int r = lane >> 2, cp = (lane & 3) * 2;
#pragma unroll
    for (int ks = 0; ks < 2; ++ks) {
        const int kb = ks * 16;
        uint32_t a[MI][4];
#pragma unroll
        for (int mi = 0; mi < MI; ++mi) {
            const bf16* ap = A + (wm * MI * 16 + mi * 16 + r) * SPAD + kb + cp;
            a[mi][0] = *(const uint32_t*)ap;
            a[mi][1] = *(const uint32_t*)(ap + 8 * SPAD);
            a[mi][2] = *(const uint32_t*)(ap + 8);
            a[mi][3] = *(const uint32_t*)(ap + 8 * SPAD + 8);
        }
        uint32_t b[4][2];
#pragma unroll
        for (int ni = 0; ni < 4; ++ni) {
            const bf16* bp = B + (wn * 32 + ni * 8 + r) * SPAD + kb + cp;
            b[ni][0] = *(const uint32_t*)bp;
            b[ni][1] = *(const uint32_t*)(bp + 8);
        }
#pragma unroll
        for (int mi = 0; mi < MI; ++mi)
#pragma unroll
            for (int ni = 0; ni < 4; ++ni)
                mma16(acc[mi][ni], a[mi][0], a[mi][1], a[mi][2], a[mi][3],
                      b[ni][0], b[ni][1]);
    }
}

// =====================================================================
// Prep: bf16 conversions. Whh reordered into 128 panels of 32 gate-rows:
// panel x, row g*8+c  <-  Whh row g*1024 + x*8 + c.
// =====================================================================
__global__ __launch_bounds__(256)
void conv_all(const float* __restrict__ emb, const float* __restrict__ Wih,
              const float* __restrict__ Whh, const float* __restrict__ Win,
              const float* __restrict__ Wout) {
    const size_t NE = (size_t)50000 * I_;
    const size_t NW1 = (size_t)G4 * I_;
    const size_t NW2 = (size_t)G4 * H_;
    const size_t NV  = (size_t)H_ * H_;
    size_t i4 = ((size_t)blockIdx.x * 256 + threadIdx.x) * 4;
    float4 v; bf16* dst;
    if (i4 < NE) { v = *(const float4*)(emb + i4); dst = g_embb + i4; }
    else if ((i4 -= NE) < NW1) { v = *(const float4*)(Wih + i4); dst = g_wihb + i4; }
    else if ((i4 -= NW1) < NW2) {
        size_t k = i4 & (H_ - 1), np = i4 >> 10;
        size_t x = np >> 5, gr = np & 31, g = gr >> 3, c = gr & 7;
        size_t n = g * H_ + x * 8 + c;
        v = *(const float4*)(Whh + n * H_ + k); dst = g_whhb + i4;
    }
    else if ((i4 -= NW2) < NV) { v = *(const float4*)(Win + (size_t)2 * H_ * H_ + i4); dst = g_winvb + i4; }
    else if ((i4 -= NV) < NV)  { v = *(const float4*)(Wout + i4); dst = g_woutb + i4; }
    else return;
    dst[0] = __float2bfloat16(v.x); dst[1] = __float2bfloat16(v.y);
    dst[2] = __float2bfloat16(v.z); dst[3] = __float2bfloat16(v.w);
}

// =====================================================================
// Embed + input GEMM. Writes g_xw in persistent-panel layout, bias folded.
// =====================================================================
__global__ __launch_bounds__(256)
void embed_gemm(const int* __restrict__ paths,
                const float* __restrict__ bih, const float* __restrict__ bhh) {
    constexpr int STG = (128 + 128) * SPAD;
    __shared__ __align__(16) bf16 smem[2 * STG];
    const uint32_t sbase = (uint32_t)__cvta_generic_to_shared(smem);

    const int tid = threadIdx.x, lane = tid & 31, warp = tid >> 5;
    const int wm = warp >> 2, wn = warp & 3;
    const int m0 = blockIdx.y * 128, n0 = blockIdx.x * 128;
    const int l = m0 >> 8;
    const int r4 = lane >> 2, c0 = (lane & 3) * 2;

    const bf16* arowp[2];
    int arow[2], acol[2];
#pragma unroll
    for (int j = 0; j < 2; ++j) {
        int ch = tid + j * 256;
        arow[j] = ch >> 2; acol[j] = (ch & 3) * 8;
        int p = (m0 & 255) + arow[j];
        arowp[j] = g_embb + (size_t)paths[p * L_ + l] * I_;
    }
    const bf16* Bb = g_wihb + (size_t)n0 * I_;

    float acc[4][4][4];
#pragma unroll
    for (int a = 0; a < 4; a++)
#pragma unroll
        for (int b = 0; b < 4; b++)
#pragma unroll
            for (int c = 0; c < 4; c++) acc[a][b][c] = 0.f;

    auto load = [&](int s, int k0) {
        uint32_t sa = sbase + s * STG * 2;
        uint32_t sb = sa + 128 * SPAD * 2;
#pragma unroll
        for (int j = 0; j < 2; ++j)
            cpa16(sa + (arow[j] * SPAD + acol[j]) * 2, arowp[j] + k0 + acol[j]);
#pragma unroll
        for (int j = 0; j < 2; ++j) {
            int ch = tid + j * 256;
            int row = ch >> 2, cc = (ch & 3) * 8;
            cpa16(sb + (row * SPAD + cc) * 2, Bb + (size_t)row * I_ + k0 + cc);
        }
    };

    load(0, 0); cpcommit();
    for (int it = 0; it < 16; ++it) {
        if (it + 1 < 16) load((it + 1) & 1, (it + 1) * 32);
        cpcommit();
        cpwait<1>();
        __syncthreads();
        const bf16* A = smem + (it & 1) * STG;
        mma_stage<4>(A, A + 128 * SPAD, wm, wn, lane, acc);
        __syncthreads();
    }

    // epilogue -> panel layout [l][x][p][g*8+c]
#pragma unroll
    for (int mi = 0; mi < 4; ++mi) {
        int m = m0 + wm * 64 + mi * 16 + r4;
        int p = m & 255;
#pragma unroll
        for (int ni = 0; ni < 4; ++ni) {
            int n = n0 + wn * 32 + ni * 8 + c0;
            int g = n >> 10, xg = (n & (H_ - 1)) >> 3;
            float* dst = g_xw + (((size_t)(l * NPER + xg) * P_ + p) * 32) + g * 8 + c0;
            float b0 = bih[n] + bhh[n], b1 = bih[n + 1] + bhh[n + 1];
            dst[0]       = acc[mi][ni][0] + b0;
            dst[1]       = acc[mi][ni][1] + b1;
            dst[256]     = acc[mi][ni][2] + b0;   // row p+8
            dst[257]     = acc[mi][ni][3] + b1;
        }
    }
}

// =====================================================================
// Persistent LSTM recurrence. 128 CTAs x 256 thr, 1 CTA/SM (141KB smem).
// CTA x owns hidden cols [8x,8x+8) x 4 gates (32 gate rows); Whh panel
// resident in smem for all 63 steps; c in registers; grid barrier per step.
// =====================================================================
__global__ __launch_bounds__(256, 1)
void lstm_persist(const int* __restrict__ lengths) {
    extern __shared__ __align__(16) bf16 dsm[];
    bf16* sB = dsm;                              // [32][B_PITCH]
    bf16* sA = dsm + 32 * B_PITCH;               // 2 stages [256][A_PITCH]
    __shared__ int slen[P_];
    const uint32_t sbase = (uint32_t)__cvta_generic_to_shared(dsm);
    const uint32_t sAoff = 32 * B_PITCH * 2;     // bytes
    const uint32_t sAstg = 256 * A_PITCH * 2;    // bytes per stage

    const int tid = threadIdx.x, lane = tid & 31, warp = tid >> 5;
    const int x = blockIdx.x;
    const int r4 = lane >> 2, c0 = (lane & 3) * 2;

    slen[tid] = lengths[tid];

    // load Whh panel (32 x 1024) into smem, once
    {
        const bf16* src = g_whhb + (size_t)x * 32 * H_;
#pragma unroll
        for (int j = 0; j < 16; ++j) {
            int ch = tid + j * 256;
            int row = ch >> 7, col = (ch & 127) * 8;
            cpa16(sbase + (row * B_PITCH + col) * 2, src + (size_t)row * H_ + col);
        }
    }
    cpcommit();

    unsigned mygen = 0;
    if (tid == 0) mygen = *(volatile unsigned*)&g_bargen;

    cpwait<0>();
    __syncthreads();

    float creg[2][2][2];
#pragma unroll
    for (int a = 0; a < 2; a++)
#pragma unroll
        for (int b = 0; b < 2; b++) { creg[a][b][0] = 0.f; creg[a][b][1] = 0.f; }

    float acc[2][4][4];

    for (int t = 0; t < L_; ++t) {
        // prefetch xw for this step into registers (hidden under GEMM)
        const float* xwb = g_xw + ((size_t)t * NPER + x) * (P_ * 32);
        float2 xf[4][4];
#pragma unroll
        for (int mi = 0; mi < 2; ++mi)
#pragma unroll
            for (int rr = 0; rr < 2; ++rr) {
                int p = warp * 32 + mi * 16 + rr * 8 + r4;
                const float2* xr2 = (const float2*)(xwb + p * 32 + c0);
#pragma unroll
                for (int g = 0; g < 4; ++g) xf[mi * 2 + rr][g] = xr2[g * 4];
            }

#pragma unroll
        for (int a = 0; a < 2; a++)
#pragma unroll
            for (int b = 0; b < 4; b++)
#pragma unroll
                for (int c = 0; c < 4; c++) acc[a][b][c] = 0.f;

        if (t > 0) {
            const bf16* hprev = ((t - 1) & 1) ? g_hbuf1 : g_hbuf0;
            auto loadA = [&](int s, int k0) {
                uint32_t sa = sbase + sAoff + s * sAstg;
#pragma unroll
                for (int j = 0; j < 8; ++j) {
                    int ch = tid + j * 256;
                    int row = ch >> 3, col = (ch & 7) * 8;
                    cpa16(sa + (row * A_PITCH + col) * 2,
                          hprev + (size_t)row * H_ + k0 + col);
                }
            };
            loadA(0, 0); cpcommit();
            for (int ch = 0; ch < 16; ++ch) {
                if (ch + 1 < 16) loadA((ch + 1) & 1, (ch + 1) * BKP);
                cpcommit();
                cpwait<1>();
                __syncthreads();
                const bf16* A = sA + (ch & 1) * 256 * A_PITCH;
#pragma unroll
                for (int ks = 0; ks < 4; ++ks) {
                    const int kb = ks * 16;
                    const int kg = ch * BKP + kb;
                    uint32_t a[2][4];
#pragma unroll
                    for (int mi = 0; mi < 2; ++mi) {
                        const bf16* ap = A + (warp * 32 + mi * 16 + r4) * A_PITCH + kb + c0;
                        a[mi][0] = *(const uint32_t*)ap;
                        a[mi][1] = *(const uint32_t*)(ap + 8 * A_PITCH);
                        a[mi][2] = *(const uint32_t*)(ap + 8);
                        a[mi][3] = *(const uint32_t*)(ap + 8 * A_PITCH + 8);
                    }
                    uint32_t b[4][2];
#pragma unroll
                    for (int ni = 0; ni < 4; ++ni) {
                        const bf16* bp = sB + (ni * 8 + r4) * B_PITCH + kg + c0;
                        b[ni][0] = *(const uint32_t*)bp;
                        b[ni][1] = *(const uint32_t*)(bp + 8);
                    }
#pragma unroll
                    for (int mi = 0; mi < 2; ++mi)
#pragma unroll
                        for (int ni = 0; ni < 4; ++ni)
                            mma16(acc[mi][ni], a[mi][0], a[mi][1], a[mi][2], a[mi][3],
                                  b[ni][0], b[ni][1]);
                }
                __syncthreads();
            }
        }

        // ---- fused LSTM epilogue (gate == ni, no transpose needed) ----
        bf16* hw = (t & 1) ? g_hbuf1 : g_hbuf0;
#pragma unroll
        for (int mi = 0; mi < 2; ++mi)
#pragma unroll
            for (int rr = 0; rr < 2; ++rr) {
                int p = warp * 32 + mi * 16 + rr * 8 + r4;
                int ai = rr * 2;
                float2 xi = xf[mi * 2 + rr][0], xg2 = xf[mi * 2 + rr][2];
                float2 xff = xf[mi * 2 + rr][1], xo = xf[mi * 2 + rr][3];
                float i0 = acc[mi][0][ai] + xi.x,  i1 = acc[mi][0][ai + 1] + xi.y;
                float f0 = acc[mi][1][ai] + xff.x, f1 = acc[mi][1][ai + 1] + xff.y;
                float g0 = acc[mi][2][ai] + xg2.x, g1 = acc[mi][2][ai + 1] + xg2.y;
                float o0 = acc[mi][3][ai] + xo.x,  o1 = acc[mi][3][ai + 1] + xo.y;
                float cn0 = sigf(f0) * creg[mi][rr][0] + sigf(i0) * tanhf(g0);
                float cn1 = sigf(f1) * creg[mi][rr][1] + sigf(i1) * tanhf(g1);
                creg[mi][rr][0] = cn0; creg[mi][rr][1] = cn1;
                float h0 = sigf(o0) * tanhf(cn0);
                float h1 = sigf(o1) * tanhf(cn1);
                __nv_bfloat162 hv(__float2bfloat16(h0), __float2bfloat16(h1));
                *(__nv_bfloat162*)&hw[(size_t)p * H_ + x * 8 + c0] = hv;
                if (slen[p] == t + 1)
                    *(__nv_bfloat162*)&g_finalb[(size_t)p * H_ + x * 8 + c0] = hv;
            }

        // ---- grid barrier ----
        __threadfence();
        __syncthreads();
        if (tid == 0) {
            ++mygen;
            unsigned a = atomicAdd(&g_barcnt, 1);
            if (a == NPER - 1) {
                *(volatile unsigned*)&g_barcnt = 0;
                __threadfence();
                atomicAdd(&g_bargen, 1);
            } else {
                while ((int)(*(volatile unsigned*)&g_bargen - mygen) < 0) {}
            }
        }
        __syncthreads();
        __threadfence();
    }
}

// =====================================================================
// Attention-path GEMMs (seq_len=1 => softmax==1 => ctx==v; q,k dead).
// =====================================================================
template <int MODE>
__global__ __launch_bounds__(256)
void gemm_attn(const float* __restrict__ bias) {
    constexpr int STG = (64 + 128) * SPAD;
    __shared__ __align__(16) bf16 smem[3 * STG];
    const uint32_t sbase = (uint32_t)__cvta_generic_to_shared(smem);

    const int tid = threadIdx.x, lane = tid & 31, warp = tid >> 5;
    const int wm = warp >> 2, wn = warp & 3;
    const int n0 = blockIdx.x * 128, p0 = blockIdx.y * 64;

    const bf16* Ab = (MODE ? g_vb : g_finalb) + (size_t)p0 * H_;
    const bf16* Bb = (MODE ? g_woutb : g_winvb) + (size_t)n0 * H_;

    float acc[2][4][4];
#pragma unroll
    for (int a = 0; a < 2; a++)
#pragma unroll
        for (int b = 0; b < 4; b++)
#pragma unroll
            for (int c = 0; c < 4; c++) acc[a][b][c] = 0.f;

    auto load = [&](int s, int k0) {
        uint32_t sa = sbase + s * STG * 2;
        uint32_t sb = sa + 64 * SPAD * 2;
        {
            int row = tid >> 2, cc = (tid & 3) * 8;
            cpa16(sa + (row * SPAD + cc) * 2, Ab + (size_t)row * H_ + k0 + cc);
        }
#pragma unroll
        for (int j = 0; j < 2; ++j) {
            int ch = tid + j * 256;
            int row = ch >> 2, cc = (ch & 3) * 8;
            cpa16(sb + (row * SPAD + cc) * 2, Bb + (size_t)row * H_ + k0 + cc);
        }
    };

    load(0, 0); cpcommit();
    load(1, 32); cpcommit();
    for (int it = 0; it < 32; ++it) {
        if (it + 2 < 32) load((it + 2) % 3, (it + 2) * 32);
        cpcommit();
        cpwait<2>();
        __syncthreads();
        const bf16* A = smem + (it % 3) * STG;
        mma_stage<2>(A, A + 64 * SPAD, wm, wn, lane, acc);
        __syncthreads();
    }

#pragma unroll
    for (int mi = 0; mi < 2; ++mi) {
        int r0 = p0 + wm * 32 + mi * 16 + (lane >> 2);
#pragma unroll
        for (int ni = 0; ni < 4; ++ni) {
            int c0 = n0 + wn * 32 + ni * 8 + (lane & 3) * 2;
            float v00 = acc[mi][ni][0] + bias[c0];
            float v01 = acc[mi][ni][1] + bias[c0 + 1];
            float v10 = acc[mi][ni][2] + bias[c0];
            float v11 = acc[mi][ni][3] + bias[c0 + 1];
            if (MODE == 0) {
                *(__nv_bfloat162*)&g_vb[(size_t)r0 * H_ + c0] =
                    __nv_bfloat162(__float2bfloat16(v00), __float2bfloat16(v01));
                *(__nv_bfloat162*)&g_vb[(size_t)(r0 + 8) * H_ + c0] =
                    __nv_bfloat162(__float2bfloat16(v10), __float2bfloat16(v11));
            } else {
                g_attn[(size_t)r0 * H_ + c0]           = v00;
                g_attn[(size_t)r0 * H_ + c0 + 1]       = v01;
                g_attn[(size_t)(r0 + 8) * H_ + c0]     = v10;
                g_attn[(size_t)(r0 + 8) * H_ + c0 + 1] = v11;
            }
        }
    }
}

// =====================================================================
// Max-pool over P + final linear + sigmoid
// =====================================================================
__global__ __launch_bounds__(1024)
void pool_out(const float* __restrict__ Wlin, const float* __restrict__ blin,
              float* __restrict__ out) {
    __shared__ float sp[H_];
    __shared__ float red[32];
    int j = threadIdx.x;
    float m = -INFINITY;
    for (int p = 0; p < P_; ++p) m = fmaxf(m, g_attn[p * H_ + j]);
    sp[j] = m;
    __syncthreads();
    for (int o = 0; o < OUTD; ++o) {
        float v = sp[j] * Wlin[o * H_ + j];
#pragma unroll
        for (int s = 16; s; s >>= 1) v += __shfl_down_sync(0xffffffffu, v, s);
        if ((j & 31) == 0) red[j >> 5] = v;
        __syncthreads();
        if (j < 32) {
            float w = red[j];
#pragma unroll
            for (int s = 16; s; s >>= 1) w += __shfl_down_sync(0xffffffffu, w, s);
            if (j == 0) out[o] = 1.f / (1.f + expf(-(w + blin[o])));
        }
        __syncthreads();
    }
}

// =====================================================================
extern "C" void kernel_launch(void* const* d_in, const int* in_sizes, int n_in,
                              void* d_out, int out_size) {
    (void)in_sizes; (void)n_in; (void)out_size;
    const int*   paths   = (const int*)d_in[0];
    const int*   lengths = (const int*)d_in[1];
    const float* emb     = (const float*)d_in[2];
    const float* Wih     = (const float*)d_in[3];
    const float* Whh     = (const float*)d_in[4];
    const float* bih     = (const float*)d_in[5];
    const float* bhh     = (const float*)d_in[6];
    const float* Win     = (const float*)d_in[7];
    const float* bin     = (const float*)d_in[8];
    const float* Wout    = (const float*)d_in[9];
    const float* bout    = (const float*)d_in[10];
    const float* Wlin    = (const float*)d_in[11];
    const float* blin    = (const float*)d_in[12];
    float* out = (float*)d_out;

    const int dynsmem = (32 * B_PITCH + 2 * 256 * A_PITCH) * 2;  // 140800 B
    cudaFuncSetAttribute(lstm_persist, cudaFuncAttributeMaxDynamicSharedMemorySize,
                         dynsmem);

    conv_all<<<33192, 256>>>(emb, Wih, Whh, Win, Wout);
    embed_gemm<<<dim3(32, 128), 256>>>(paths, bih, bhh);
    lstm_persist<<<NPER, 256, dynsmem>>>(lengths);
    gemm_attn<0><<<dim3(8, 4), 256>>>(bin + 2 * H_);
    gemm_attn<1><<<dim3(8, 4), 256>>>(bout);
    pool_out<<<1, 1024>>>(Wlin, blin, out);
}